// round 3
// baseline (speedup 1.0000x reference)
#include <cuda_runtime.h>
#include <cuda_bf16.h>
#include <cstdint>

// Problem constants (fixed by setup_inputs)
#define B_   8
#define NCH  32      // centers channels
#define N_   16      // gaussians per (b,k)
#define K_   16
#define H_   128
#define W_   128
#define BK_  (B_ * K_)          // 128
#define HW_  (H_ * W_)          // 16384
#define NPIX ((long long)BK_ * HW_)  // 2097152

#define BLOCKS_PER_BK 4
#define ROWS_PER_BLK  (H_ / BLOCKS_PER_BK)   // 32
#define GRID_ (BK_ * BLOCKS_PER_BK)          // 512

// Cross-block accumulator (zero-initialized at module load; reset in-kernel
// after each use so graph replays see the same initial state).
__device__ double   g_acc;
__device__ unsigned g_count;

// ---------------------------------------------------------------------------
// Single fused kernel.
// Block = one (b,k) x 32-row tile. Builds its own separable factor tables
// fx[16][128], fy[32][16] in shared memory, then evaluates
//   g(y,x) = sum_n fy[y][n] * fx[n][x],  p = sigmoid(g), masked BCE,
// reduces, and the last block finalizes + broadcasts the loss.
// ---------------------------------------------------------------------------
__global__ void __launch_bounds__(256) gl_fused(
        const float* __restrict__ centers,
        const float* __restrict__ radius,
        const float* __restrict__ mask,
        const int*   __restrict__ ind,
        const float* __restrict__ target,
        const float* __restrict__ peak,
        float* __restrict__ out, int out_n) {
    int blk     = blockIdx.x;
    int bk      = blk >> 2;          // / BLOCKS_PER_BK
    int quarter = blk & 3;
    int tid     = threadIdx.x;
    int x       = tid & 127;
    int ysub    = tid >> 7;          // 0 or 1

    int b = bk >> 4;

    // 16-byte alignment is required: s_fy is read via float4 (LDS.128).
    __shared__ __align__(16) float s_fx[N_ * W_];            // [n][x]   8 KB
    __shared__ __align__(16) float s_fy[ROWS_PER_BLK * N_];  // [row][n] 2 KB
    __shared__ __align__(16) float s_c[32];                  // cx,cy per n
    __shared__ float s_inv;
    __shared__ float s_wsum[8];
    __shared__ int   s_last;

    int p = ind[bk];
    if (tid < 32) {
        // channel tid of gathered pred, shifted by peak (x for even, y for odd)
        s_c[tid] = centers[(b * NCH + tid) * HW_ + p] + peak[bk * 2 + (tid & 1)];
    }
    if (tid == 0) {
        float r = radius[b * HW_ + p];
        s_inv = -0.5f / (r * r);
    }
    __syncthreads();

    float inv = s_inv;
    // fx: 2048 entries, 8 per thread
#pragma unroll
    for (int i = tid; i < N_ * W_; i += 256) {
        int n  = i >> 7;
        int xx = i & 127;
        float d = s_c[2 * n] - (float)xx;
        s_fx[i] = __expf(inv * d * d);
    }
    // fy: 512 entries, 2 per thread
#pragma unroll
    for (int i = tid; i < ROWS_PER_BLK * N_; i += 256) {
        int row = i >> 4;
        int n   = i & 15;
        float d = s_c[2 * n + 1] - (float)(quarter * ROWS_PER_BLK + row);
        s_fy[i] = __expf(inv * d * d);
    }
    __syncthreads();

    float fx[16];
#pragma unroll
    for (int n = 0; n < 16; n++)
        fx[n] = s_fx[n * W_ + x];

    float m = mask[bk];
    const float* tg = target + (long long)bk * HW_ + quarter * ROWS_PER_BLK * W_;

    float acc = 0.0f;
#pragma unroll
    for (int it = 0; it < ROWS_PER_BLK / 2; it++) {
        int yloc = ysub + 2 * it;
        const float4* fy4 = (const float4*)&s_fy[yloc * N_];
        float g0 = 0.f, g1 = 0.f, g2 = 0.f, g3 = 0.f;
#pragma unroll
        for (int q = 0; q < 4; q++) {
            float4 v = fy4[q];   // warp-uniform broadcast
            g0 = fmaf(v.x, fx[4 * q + 0], g0);
            g1 = fmaf(v.y, fx[4 * q + 1], g1);
            g2 = fmaf(v.z, fx[4 * q + 2], g2);
            g3 = fmaf(v.w, fx[4 * q + 3], g3);
        }
        float g = (g0 + g1) + (g2 + g3);

        // sigmoid (precise division to match reference rounding)
        float e  = __expf(-g);
        float pr = 1.0f / (1.0f + e);

        float xm = pr * m;
        float ym = tg[yloc * W_ + x] * m;

        // p >= 0.5 when m==1, so 1-xm is exact (Sterbenz) and log(1-xm)
        // equals log1p(-xm); log(0) -> -inf -> clamped to -100.
        float lx  = fmaxf(__logf(xm), -100.0f);
        float l1x = fmaxf(__logf(1.0f - xm), -100.0f);

        acc += ym * lx + (1.0f - ym) * l1x;
    }

    // warp reduce
#pragma unroll
    for (int o = 16; o > 0; o >>= 1)
        acc += __shfl_down_sync(0xffffffffu, acc, o);
    if ((tid & 31) == 0) s_wsum[tid >> 5] = acc;
    __syncthreads();

    if (tid == 0) {
        float s = 0.f;
#pragma unroll
        for (int w = 0; w < 8; w++) s += s_wsum[w];
        atomicAdd(&g_acc, (double)s);
        __threadfence();
        unsigned old = atomicAdd(&g_count, 1u);
        s_last = (old == GRID_ - 1) ? 1 : 0;
    }
    __syncthreads();

    if (s_last) {
        double a = g_acc;   // all adds visible: fence + counter protocol
        float loss = (float)(-a / (double)NPIX);
        for (int i = tid; i < out_n; i += 256)
            out[i] = loss;
        if (tid == 0) {     // reset for next graph replay
            g_acc = 0.0;
            g_count = 0u;
        }
    }
}

extern "C" void kernel_launch(void* const* d_in, const int* in_sizes, int n_in,
                              void* d_out, int out_size) {
    const float* centers = (const float*)d_in[0];
    const float* radius  = (const float*)d_in[1];
    const float* mask    = (const float*)d_in[2];
    const int*   ind     = (const int*)d_in[3];
    const float* target  = (const float*)d_in[4];
    const float* peak    = (const float*)d_in[5];
    float* out = (float*)d_out;

    gl_fused<<<GRID_, 256>>>(centers, radius, mask, ind, target, peak,
                             out, out_size);
}

// round 5
// speedup vs baseline: 1.1805x; 1.1805x over previous
#include <cuda_runtime.h>
#include <cuda_bf16.h>
#include <cstdint>

// Problem constants (fixed by setup_inputs)
#define B_   8
#define NCH  32      // centers channels
#define N_   16      // gaussians per (b,k)
#define K_   16
#define H_   128
#define W_   128
#define BK_  (B_ * K_)          // 128
#define HW_  (H_ * W_)          // 16384
#define NPIX ((long long)BK_ * HW_)  // 2097152

#define BLOCKS_PER_BK 8
#define ROWS_PER_BLK  (H_ / BLOCKS_PER_BK)   // 16
#define GRID_ (BK_ * BLOCKS_PER_BK)          // 1024

// Cross-block accumulator (zero-initialized at module load; reset in-kernel
// after each use so graph replays see the same initial state).
__device__ double   g_acc;     // holds sum of BCE terms (negative values)
__device__ unsigned g_count;

// ---------------------------------------------------------------------------
// Single fused kernel. Block = one (b,k) x 16-row tile.
// Builds separable factor tables fx[16][128], fy[16][16] in smem, then
//   g(y,x) = sum_n fy[y][n]*fx[n][x],  p = sigmoid(g), masked BCE, reduce.
// SIGN CONVENTION (single, both paths): acc accumulates
//   term = y*log(p*m) + (1-y*m)*log(1-p*m)   (<= 0)
// and finalize computes loss = -g_acc / NPIX.
// Fast path (m == 1): term = -(log1p(e^-g) + (1-y)*g).
// ---------------------------------------------------------------------------
__global__ void __launch_bounds__(256) gl_fused(
        const float* __restrict__ centers,
        const float* __restrict__ radius,
        const float* __restrict__ mask,
        const int*   __restrict__ ind,
        const float* __restrict__ target,
        const float* __restrict__ peak,
        float* __restrict__ out, int out_n) {
    int blk    = blockIdx.x;
    int bk     = blk >> 3;           // / BLOCKS_PER_BK
    int eighth = blk & 7;
    int tid    = threadIdx.x;
    int x      = tid & 127;
    int ysub   = tid >> 7;           // 0 or 1

    int b = bk >> 4;

    // 16-byte alignment: s_fy is read via float4 (LDS.128).
    __shared__ __align__(16) float s_fx[N_ * W_];            // [n][x]   8 KB
    __shared__ __align__(16) float s_fy[ROWS_PER_BLK * N_];  // [row][n] 1 KB
    __shared__ __align__(16) float s_c[32];                  // cx,cy per n
    __shared__ float s_inv;
    __shared__ float s_wsum[8];
    __shared__ int   s_last;

    int p = ind[bk];
    if (tid < 32) {
        // channel tid of gathered pred, shifted by peak (x even, y odd)
        s_c[tid] = centers[(b * NCH + tid) * HW_ + p] + peak[bk * 2 + (tid & 1)];
    }
    if (tid == 0) {
        float r = radius[b * HW_ + p];
        s_inv = -0.5f / (r * r);
    }
    __syncthreads();

    float inv = s_inv;
    // fx: 2048 entries, 8 per thread
#pragma unroll
    for (int i = tid; i < N_ * W_; i += 256) {
        int n  = i >> 7;
        int xx = i & 127;
        float d = s_c[2 * n] - (float)xx;
        s_fx[i] = __expf(inv * d * d);
    }
    // fy: 256 entries, 1 per thread
    {
        int row = tid >> 4;
        int n   = tid & 15;
        float d = s_c[2 * n + 1] - (float)(eighth * ROWS_PER_BLK + row);
        s_fy[tid] = __expf(inv * d * d);
    }
    __syncthreads();

    float fx[16];
#pragma unroll
    for (int n = 0; n < 16; n++)
        fx[n] = s_fx[n * W_ + x];

    float m = mask[bk];
    const float* tg = target + (long long)bk * HW_ + eighth * ROWS_PER_BLK * W_;

    float acc = 0.0f;   // sum of terms (negative)
    if (m == 1.0f) {
        // ---- fast path: one exp + one log per pixel, no division ----
#pragma unroll
        for (int it = 0; it < ROWS_PER_BLK / 2; it++) {
            int yloc = ysub + 2 * it;
            const float4* fy4 = (const float4*)&s_fy[yloc * N_];
            float g0 = 0.f, g1 = 0.f, g2 = 0.f, g3 = 0.f;
#pragma unroll
            for (int q = 0; q < 4; q++) {
                float4 v = fy4[q];   // warp-uniform broadcast
                g0 = fmaf(v.x, fx[4 * q + 0], g0);
                g1 = fmaf(v.y, fx[4 * q + 1], g1);
                g2 = fmaf(v.z, fx[4 * q + 2], g2);
                g3 = fmaf(v.w, fx[4 * q + 3], g3);
            }
            float g = (g0 + g1) + (g2 + g3);       // g > 0
            float y = tg[yloc * W_ + x];
            float e  = __expf(-g);                 // e in (0, 1]
            float sp = __logf(1.0f + e);           // softplus(-g)
            // term = y*log(p)+(1-y)*log(1-p) = -(sp + (1-y)*g)
            acc -= fmaf(1.0f - y, g, sp);
        }
    } else {
        // ---- general path (matches reference construction exactly) ----
#pragma unroll
        for (int it = 0; it < ROWS_PER_BLK / 2; it++) {
            int yloc = ysub + 2 * it;
            const float4* fy4 = (const float4*)&s_fy[yloc * N_];
            float g0 = 0.f, g1 = 0.f, g2 = 0.f, g3 = 0.f;
#pragma unroll
            for (int q = 0; q < 4; q++) {
                float4 v = fy4[q];
                g0 = fmaf(v.x, fx[4 * q + 0], g0);
                g1 = fmaf(v.y, fx[4 * q + 1], g1);
                g2 = fmaf(v.z, fx[4 * q + 2], g2);
                g3 = fmaf(v.w, fx[4 * q + 3], g3);
            }
            float g = (g0 + g1) + (g2 + g3);
            float e  = __expf(-g);
            float pr = 1.0f / (1.0f + e);
            float xm = pr * m;
            float ym = tg[yloc * W_ + x] * m;
            float lx  = fmaxf(__logf(xm), -100.0f);
            float l1x = fmaxf(__logf(1.0f - xm), -100.0f);
            acc += ym * lx + (1.0f - ym) * l1x;   // term, same convention
        }
    }

    // warp reduce
#pragma unroll
    for (int o = 16; o > 0; o >>= 1)
        acc += __shfl_down_sync(0xffffffffu, acc, o);
    if ((tid & 31) == 0) s_wsum[tid >> 5] = acc;
    __syncthreads();

    if (tid == 0) {
        float s = 0.f;
#pragma unroll
        for (int w = 0; w < 8; w++) s += s_wsum[w];
        atomicAdd(&g_acc, (double)s);             // g_acc = sum(terms)
        __threadfence();
        unsigned old = atomicAdd(&g_count, 1u);
        s_last = (old == GRID_ - 1) ? 1 : 0;
    }
    __syncthreads();

    if (s_last) {
        double a = g_acc;   // all adds visible: fence + counter protocol
        float loss = (float)(-a / (double)NPIX);  // loss = -mean(terms)
        for (int i = tid; i < out_n; i += 256)
            out[i] = loss;
        if (tid == 0) {     // reset for next graph replay
            g_acc = 0.0;
            g_count = 0u;
        }
    }
}

extern "C" void kernel_launch(void* const* d_in, const int* in_sizes, int n_in,
                              void* d_out, int out_size) {
    const float* centers = (const float*)d_in[0];
    const float* radius  = (const float*)d_in[1];
    const float* mask    = (const float*)d_in[2];
    const int*   ind     = (const int*)d_in[3];
    const float* target  = (const float*)d_in[4];
    const float* peak    = (const float*)d_in[5];
    float* out = (float*)d_out;

    gl_fused<<<GRID_, 256>>>(centers, radius, mask, ind, target, peak,
                             out, out_size);
}

// round 6
// speedup vs baseline: 1.3732x; 1.1633x over previous
#include <cuda_runtime.h>
#include <cuda_bf16.h>
#include <cstdint>

// Problem constants (fixed by setup_inputs)
#define B_   8
#define NCH  32      // centers channels
#define N_   16      // gaussians per (b,k)
#define K_   16
#define H_   128
#define W_   128
#define BK_  (B_ * K_)          // 128
#define HW_  (H_ * W_)          // 16384
#define NPIX ((long long)BK_ * HW_)  // 2097152

#define GRID_ BK_                // one block per (b,k): 128 blocks, single wave

// Cross-block accumulator (zero-initialized at module load; reset in-kernel
// after each use so graph replays see the same initial state).
__device__ double   g_acc;     // holds sum of BCE terms (negative values)
__device__ unsigned g_count;

// ---------------------------------------------------------------------------
// Single fused kernel. Block = one (b,k), 1024 threads, all 128 rows.
// Builds separable factor tables fx[16][128], fy[128][16] in smem, then
//   g(y,x) = sum_n fy[y][n]*fx[n][x],  p = sigmoid(g), masked BCE, reduce.
// SIGN CONVENTION (both paths): acc accumulates
//   term = y*log(p*m) + (1-y*m)*log(1-p*m)   (<= 0)
// and finalize computes loss = -g_acc / NPIX.
// Fast path (m == 1): term = -(log1p(e^-g) + (1-y)*g)  [exact identity].
// ---------------------------------------------------------------------------
__global__ void __launch_bounds__(1024) gl_fused(
        const float* __restrict__ centers,
        const float* __restrict__ radius,
        const float* __restrict__ mask,
        const int*   __restrict__ ind,
        const float* __restrict__ target,
        const float* __restrict__ peak,
        float* __restrict__ out, int out_n) {
    int bk   = blockIdx.x;
    int tid  = threadIdx.x;
    int x    = tid & 127;
    int ygrp = tid >> 7;            // 0..7, warp-uniform
    int b    = bk >> 4;

    // 16-byte alignment: s_fy is read via float4 (LDS.128).
    __shared__ __align__(16) float s_fx[N_ * W_];   // [n][x]   8 KB
    __shared__ __align__(16) float s_fy[H_ * N_];   // [y][n]   8 KB
    __shared__ __align__(16) float s_c[32];         // cx,cy per n
    __shared__ float s_inv;
    __shared__ float s_wsum[32];
    __shared__ int   s_last;

    int p = ind[bk];
    if (tid < 32) {
        // channel tid of gathered pred, shifted by peak (x even, y odd)
        s_c[tid] = centers[(b * NCH + tid) * HW_ + p] + peak[bk * 2 + (tid & 1)];
    }
    if (tid == 0) {
        float r = radius[b * HW_ + p];
        s_inv = -0.5f / (r * r);
    }
    __syncthreads();

    float inv = s_inv;
    // fx: 2048 entries, 2 per thread
#pragma unroll
    for (int i = tid; i < N_ * W_; i += 1024) {
        int n  = i >> 7;
        int xx = i & 127;
        float d = s_c[2 * n] - (float)xx;
        s_fx[i] = __expf(inv * d * d);
    }
    // fy: 2048 entries, 2 per thread, layout [y][n]
#pragma unroll
    for (int i = tid; i < H_ * N_; i += 1024) {
        int y = i >> 4;
        int n = i & 15;
        float d = s_c[2 * n + 1] - (float)y;
        s_fy[i] = __expf(inv * d * d);
    }
    __syncthreads();

    float fx[16];
#pragma unroll
    for (int n = 0; n < 16; n++)
        fx[n] = s_fx[n * W_ + x];

    float m = mask[bk];
    const float* tg = target + (long long)bk * HW_;

    float acc = 0.0f;   // sum of terms (negative)
    if (m == 1.0f) {
        // ---- fast path: one exp + one log per pixel, no division ----
#pragma unroll
        for (int it = 0; it < 16; it++) {
            int y = ygrp * 16 + it;              // warp-uniform row
            const float4* fy4 = (const float4*)&s_fy[y * N_];
            float g0 = 0.f, g1 = 0.f, g2 = 0.f, g3 = 0.f;
#pragma unroll
            for (int q = 0; q < 4; q++) {
                float4 v = fy4[q];   // warp-uniform broadcast
                g0 = fmaf(v.x, fx[4 * q + 0], g0);
                g1 = fmaf(v.y, fx[4 * q + 1], g1);
                g2 = fmaf(v.z, fx[4 * q + 2], g2);
                g3 = fmaf(v.w, fx[4 * q + 3], g3);
            }
            float g = (g0 + g1) + (g2 + g3);     // g > 0
            float yt = tg[y * W_ + x];
            float e  = __expf(-g);               // e in (0, 1]
            float sp = __logf(1.0f + e);         // softplus(-g)
            // term = y*log(p)+(1-y)*log(1-p) = -(sp + (1-y)*g)
            acc -= fmaf(1.0f - yt, g, sp);
        }
    } else {
        // ---- general path (matches reference construction exactly) ----
#pragma unroll
        for (int it = 0; it < 16; it++) {
            int y = ygrp * 16 + it;
            const float4* fy4 = (const float4*)&s_fy[y * N_];
            float g0 = 0.f, g1 = 0.f, g2 = 0.f, g3 = 0.f;
#pragma unroll
            for (int q = 0; q < 4; q++) {
                float4 v = fy4[q];
                g0 = fmaf(v.x, fx[4 * q + 0], g0);
                g1 = fmaf(v.y, fx[4 * q + 1], g1);
                g2 = fmaf(v.z, fx[4 * q + 2], g2);
                g3 = fmaf(v.w, fx[4 * q + 3], g3);
            }
            float g = (g0 + g1) + (g2 + g3);
            float e  = __expf(-g);
            float pr = 1.0f / (1.0f + e);
            float xm = pr * m;
            float ym = tg[y * W_ + x] * m;
            float lx  = fmaxf(__logf(xm), -100.0f);
            float l1x = fmaxf(__logf(1.0f - xm), -100.0f);
            acc += ym * lx + (1.0f - ym) * l1x;  // term, same convention
        }
    }

    // warp reduce
#pragma unroll
    for (int o = 16; o > 0; o >>= 1)
        acc += __shfl_down_sync(0xffffffffu, acc, o);
    if ((tid & 31) == 0) s_wsum[tid >> 5] = acc;
    __syncthreads();

    if (tid < 32) {
        float s = s_wsum[tid];
#pragma unroll
        for (int o = 16; o > 0; o >>= 1)
            s += __shfl_down_sync(0xffffffffu, s, o);
        if (tid == 0) {
            atomicAdd(&g_acc, (double)s);        // g_acc = sum(terms)
            __threadfence();
            unsigned old = atomicAdd(&g_count, 1u);
            s_last = (old == GRID_ - 1) ? 1 : 0;
        }
    }
    __syncthreads();

    if (s_last) {
        double a = g_acc;   // all adds visible: fence + counter protocol
        float loss = (float)(-a / (double)NPIX); // loss = -mean(terms)
        for (int i = tid; i < out_n; i += 1024)
            out[i] = loss;
        if (tid == 0) {     // reset for next graph replay
            g_acc = 0.0;
            g_count = 0u;
        }
    }
}

extern "C" void kernel_launch(void* const* d_in, const int* in_sizes, int n_in,
                              void* d_out, int out_size) {
    const float* centers = (const float*)d_in[0];
    const float* radius  = (const float*)d_in[1];
    const float* mask    = (const float*)d_in[2];
    const int*   ind     = (const int*)d_in[3];
    const float* target  = (const float*)d_in[4];
    const float* peak    = (const float*)d_in[5];
    float* out = (float*)d_out;

    gl_fused<<<GRID_, 1024>>>(centers, radius, mask, ind, target, peak,
                              out, out_size);
}